// round 1
// baseline (speedup 1.0000x reference)
#include <cuda_runtime.h>
#include <math.h>

// Problem dims (fixed instance)
#define B_   2
#define N_   2048
#define D_   768
#define H_   12
#define DH_  64
#define M_   3072
#define R_   (B_*N_)          // 4096 token rows
#define QKVC (3*H_*DH_)       // 2304

// ---------------- scratch (device globals; no allocations allowed) ---------
__device__ float g_h[(size_t)R_*D_];
__device__ float g_qkv[(size_t)R_*QKVC];
__device__ float g_scores[(size_t)B_*H_*N_*N_];
__device__ float g_attnout[(size_t)R_*D_];
__device__ float g_x1[(size_t)R_*D_];
__device__ float g_ffn[(size_t)R_*M_];

// ---------------- LayerNorm: one block (256 thr) per row of 768 ------------
__global__ void ln_kernel(const float* __restrict__ x,
                          const float* __restrict__ gamma,
                          const float* __restrict__ beta,
                          float* __restrict__ out)
{
    const int row = blockIdx.x;
    const float* xr = x + (long)row * D_;
    float v[3];
    float s = 0.f, s2 = 0.f;
    #pragma unroll
    for (int i = 0; i < 3; i++) {
        v[i] = xr[threadIdx.x + i*256];
        s  += v[i];
        s2 += v[i]*v[i];
    }
    // block reduce (sum, sumsq)
    #pragma unroll
    for (int o = 16; o > 0; o >>= 1) {
        s  += __shfl_xor_sync(0xffffffffu, s,  o);
        s2 += __shfl_xor_sync(0xffffffffu, s2, o);
    }
    __shared__ float sa[8], sb[8];
    int w = threadIdx.x >> 5, l = threadIdx.x & 31;
    if (l == 0) { sa[w] = s; sb[w] = s2; }
    __syncthreads();
    s = 0.f; s2 = 0.f;
    #pragma unroll
    for (int i = 0; i < 8; i++) { s += sa[i]; s2 += sb[i]; }

    const float mean = s * (1.0f / D_);
    const float var  = s2 * (1.0f / D_) - mean*mean;
    const float rstd = rsqrtf(var + 1e-5f);
    float* o = out + (long)row * D_;
    #pragma unroll
    for (int i = 0; i < 3; i++) {
        int c = threadIdx.x + i*256;
        o[c] = (v[i] - mean) * rstd * gamma[c] + beta[c];
    }
}

// ---------------- Softmax over rows of length 2048, in-place ---------------
__global__ void softmax_kernel(float* __restrict__ s)
{
    float4* p = reinterpret_cast<float4*>(s + (size_t)blockIdx.x * N_);
    const int t = threadIdx.x;
    float4 a = p[t], b = p[t + 256];

    float m = fmaxf(fmaxf(fmaxf(a.x, a.y), fmaxf(a.z, a.w)),
                    fmaxf(fmaxf(b.x, b.y), fmaxf(b.z, b.w)));
    #pragma unroll
    for (int o = 16; o > 0; o >>= 1) m = fmaxf(m, __shfl_xor_sync(0xffffffffu, m, o));
    __shared__ float sm[8];
    int w = t >> 5, l = t & 31;
    if (l == 0) sm[w] = m;
    __syncthreads();
    m = sm[0];
    #pragma unroll
    for (int i = 1; i < 8; i++) m = fmaxf(m, sm[i]);

    a.x = __expf(a.x - m); a.y = __expf(a.y - m); a.z = __expf(a.z - m); a.w = __expf(a.w - m);
    b.x = __expf(b.x - m); b.y = __expf(b.y - m); b.z = __expf(b.z - m); b.w = __expf(b.w - m);
    float sum = a.x + a.y + a.z + a.w + b.x + b.y + b.z + b.w;
    #pragma unroll
    for (int o = 16; o > 0; o >>= 1) sum += __shfl_xor_sync(0xffffffffu, sum, o);
    __shared__ float ss[8];
    if (l == 0) ss[w] = sum;
    __syncthreads();
    sum = 0.f;
    #pragma unroll
    for (int i = 0; i < 8; i++) sum += ss[i];

    const float inv = 1.0f / sum;
    a.x *= inv; a.y *= inv; a.z *= inv; a.w *= inv;
    b.x *= inv; b.y *= inv; b.z *= inv; b.w *= inv;
    p[t] = a; p[t + 256] = b;
}

// ---------------- Generic tiled SGEMM with fused epilogue ------------------
// C[z] = act( alpha * A[z] @ op(B[z]) + bias ) + residual
// z-batch offsets: off = (z/zdiv)*OUTER + (z%zdiv)*INNER  per tensor.
// bias: nullptr=none; ldbias>0 => 2D bias[row*ldbias+col]; ldbias==0 => bias[col]
template<int BM, int BN, int BK, int TM, int TN, bool TRANSB, bool GELU>
__global__ void gemm_kernel(
    const float* __restrict__ A, const float* __restrict__ B,
    const float* __restrict__ bias, const float* __restrict__ residual,
    float* __restrict__ C,
    int M, int N, int K, int lda, int ldb, int ldc,
    float alpha, int zdiv,
    long Aout, long Ain, long Bout, long Bin, long Cout, long Cin,
    long biasOut, long biasIn, int ldbias)
{
    constexpr int THREADS = (BM/TM)*(BN/TN);
    __shared__ float As[BK][BM];
    __shared__ float Bs[BK][BN];

    const int z  = blockIdx.z;
    const int zo = z / zdiv;
    const int zi = z - zo*zdiv;
    A += zo*Aout + zi*Ain;
    B += zo*Bout + zi*Bin;
    C += zo*Cout + zi*Cin;
    if (bias)     bias     += zo*biasOut + zi*biasIn;
    if (residual) residual += zo*Cout    + zi*Cin;

    const int bm  = blockIdx.y * BM;
    const int bn  = blockIdx.x * BN;
    const int tid = threadIdx.x;
    const int tr  = tid / (BN/TN);
    const int tc  = tid % (BN/TN);

    float acc[TM][TN];
    #pragma unroll
    for (int i = 0; i < TM; i++)
        #pragma unroll
        for (int j = 0; j < TN; j++) acc[i][j] = 0.f;

    constexpr int A_ITERS = (BM*BK/4)/THREADS;
    constexpr int B_ITERS = (BK*BN/4)/THREADS;

    for (int k0 = 0; k0 < K; k0 += BK) {
        #pragma unroll
        for (int it = 0; it < A_ITERS; it++) {
            int i = tid + it*THREADS;
            int row = i / (BK/4), kc = (i % (BK/4))*4;
            float4 v4 = *reinterpret_cast<const float4*>(&A[(long)(bm+row)*lda + k0 + kc]);
            As[kc+0][row] = v4.x; As[kc+1][row] = v4.y;
            As[kc+2][row] = v4.z; As[kc+3][row] = v4.w;
        }
        if (TRANSB) {
            #pragma unroll
            for (int it = 0; it < B_ITERS; it++) {
                int i = tid + it*THREADS;
                int row = i / (BK/4), kc = (i % (BK/4))*4;
                float4 v4 = *reinterpret_cast<const float4*>(&B[(long)(bn+row)*ldb + k0 + kc]);
                Bs[kc+0][row] = v4.x; Bs[kc+1][row] = v4.y;
                Bs[kc+2][row] = v4.z; Bs[kc+3][row] = v4.w;
            }
        } else {
            #pragma unroll
            for (int it = 0; it < B_ITERS; it++) {
                int i = tid + it*THREADS;
                int row = i / (BN/4), nc = (i % (BN/4))*4;
                *reinterpret_cast<float4*>(&Bs[row][nc]) =
                    *reinterpret_cast<const float4*>(&B[(long)(k0+row)*ldb + bn + nc]);
            }
        }
        __syncthreads();
        #pragma unroll
        for (int k = 0; k < BK; k++) {
            float ra[TM], rb[TN];
            #pragma unroll
            for (int i = 0; i < TM; i++) ra[i] = As[k][tr*TM + i];
            #pragma unroll
            for (int j = 0; j < TN; j++) rb[j] = Bs[k][tc*TN + j];
            #pragma unroll
            for (int i = 0; i < TM; i++)
                #pragma unroll
                for (int j = 0; j < TN; j++)
                    acc[i][j] += ra[i] * rb[j];
        }
        __syncthreads();
    }

    #pragma unroll
    for (int i = 0; i < TM; i++) {
        const int row = bm + tr*TM + i;
        #pragma unroll
        for (int j = 0; j < TN; j++) {
            const int col = bn + tc*TN + j;
            float v = acc[i][j] * alpha;
            if (bias) v += (ldbias > 0) ? bias[(long)row*ldbias + col] : bias[col];
            if (GELU) v = 0.5f * v * (1.0f + erff(v * 0.70710678118654752f));
            if (residual) v += residual[(long)row*ldc + col];
            C[(long)row*ldc + col] = v;
        }
    }
}

// ---------------------------------------------------------------------------
extern "C" void kernel_launch(void* const* d_in, const int* in_sizes, int n_in,
                              void* d_out, int out_size)
{
    const float* x      = (const float*)d_in[0];
    const float* Wqkv   = (const float*)d_in[1];
    const float* Wout   = (const float*)d_in[2];
    const float* gamma1 = (const float*)d_in[3];
    const float* beta1  = (const float*)d_in[4];
    const float* gamma2 = (const float*)d_in[5];
    const float* beta2  = (const float*)d_in[6];
    const float* W1     = (const float*)d_in[7];
    const float* b1     = (const float*)d_in[8];
    const float* W2     = (const float*)d_in[9];
    const float* b2     = (const float*)d_in[10];
    const float* abias  = (const float*)d_in[11];
    float* out = (float*)d_out;

    float *h, *qkv, *sc, *ao, *x1, *ffn;
    cudaGetSymbolAddress((void**)&h,   g_h);
    cudaGetSymbolAddress((void**)&qkv, g_qkv);
    cudaGetSymbolAddress((void**)&sc,  g_scores);
    cudaGetSymbolAddress((void**)&ao,  g_attnout);
    cudaGetSymbolAddress((void**)&x1,  g_x1);
    cudaGetSymbolAddress((void**)&ffn, g_ffn);

    // 1. h = LN(x; gamma1, beta1)
    ln_kernel<<<R_, 256>>>(x, gamma1, beta1, h);

    // 2. qkv = h @ Wqkv   [4096 x 2304]
    gemm_kernel<128,128,8,8,8,false,false><<<dim3(QKVC/128, R_/128, 1), 256>>>(
        h, Wqkv, nullptr, nullptr, qkv,
        R_, QKVC, D_, D_, QKVC, QKVC,
        1.0f, 1, 0,0, 0,0, 0,0, 0,0, 0);

    // 3. scores[b,h] = (q @ k^T) * scale + attn_bias[h]
    //    (softmax(d)*softmax(bias) renormalized == softmax(d + bias))
    gemm_kernel<128,128,8,8,8,true,false><<<dim3(N_/128, N_/128, B_*H_), 256>>>(
        qkv /*q*/, qkv + H_*DH_ /*k*/, abias, nullptr, sc,
        N_, N_, DH_, QKVC, QKVC, N_,
        0.125f, H_,
        (long)N_*QKVC, (long)DH_,          // A offsets (b, h)
        (long)N_*QKVC, (long)DH_,          // B offsets
        (long)H_*N_*N_, (long)N_*N_,       // C offsets
        0L, (long)N_*N_, N_);              // bias offsets (h only), 2D

    // 4. softmax rows (24 * 2048 rows of 2048)
    softmax_kernel<<<B_*H_*N_, 256>>>(sc);

    // 5. attnout[b,h] = attn @ v     (N=64 per head)
    gemm_kernel<64,64,16,4,4,false,false><<<dim3(1, N_/64, B_*H_), 256>>>(
        sc, qkv + 2*H_*DH_ /*v*/, nullptr, nullptr, ao,
        N_, DH_, N_, N_, QKVC, D_,
        1.0f, H_,
        (long)H_*N_*N_, (long)N_*N_,
        (long)N_*QKVC, (long)DH_,
        (long)N_*D_, (long)DH_,
        0L, 0L, 0);

    // 6. x1 = attnout @ Wout + x
    gemm_kernel<128,128,8,8,8,false,false><<<dim3(D_/128, R_/128, 1), 256>>>(
        ao, Wout, nullptr, x, x1,
        R_, D_, D_, D_, D_, D_,
        1.0f, 1, 0,0, 0,0, 0,0, 0,0, 0);

    // 7. h = LN(x1; gamma2, beta2)
    ln_kernel<<<R_, 256>>>(x1, gamma2, beta2, h);

    // 8. ffn = gelu(h @ W1 + b1)
    gemm_kernel<128,128,8,8,8,false,true><<<dim3(M_/128, R_/128, 1), 256>>>(
        h, W1, b1, nullptr, ffn,
        R_, M_, D_, D_, M_, M_,
        1.0f, 1, 0,0, 0,0, 0,0, 0,0, 0);

    // 9. out = ffn @ W2 + b2 + x1
    gemm_kernel<128,128,8,8,8,false,false><<<dim3(D_/128, R_/128, 1), 256>>>(
        ffn, W2, b2, x1, out,
        R_, D_, M_, M_, D_, D_,
        1.0f, 1, 0,0, 0,0, 0,0, 0,0, 0);
}

// round 2
// speedup vs baseline: 2.3837x; 2.3837x over previous
#include <cuda_runtime.h>
#include <math.h>

// Problem dims (fixed instance)
#define B_   2
#define N_   2048
#define D_   768
#define H_   12
#define DH_  64
#define M_   3072
#define R_   (B_*N_)          // 4096 token rows
#define QKVC (3*H_*DH_)       // 2304

// ---------------- scratch (device globals; no allocations allowed) ---------
__device__ float g_h[(size_t)R_*D_];
__device__ float g_qkv[(size_t)R_*QKVC];
__device__ float g_scores[(size_t)B_*H_*N_*N_];
__device__ float g_attnout[(size_t)R_*D_];
__device__ float g_x1[(size_t)R_*D_];
__device__ float g_ffn[(size_t)R_*M_];

// ---------------- LayerNorm: one block (256 thr) per row of 768 ------------
__global__ void ln_kernel(const float* __restrict__ x,
                          const float* __restrict__ gamma,
                          const float* __restrict__ beta,
                          float* __restrict__ out)
{
    const int row = blockIdx.x;
    const float* xr = x + (long)row * D_;
    float v[3];
    float s = 0.f, s2 = 0.f;
    #pragma unroll
    for (int i = 0; i < 3; i++) {
        v[i] = xr[threadIdx.x + i*256];
        s  += v[i];
        s2 += v[i]*v[i];
    }
    #pragma unroll
    for (int o = 16; o > 0; o >>= 1) {
        s  += __shfl_xor_sync(0xffffffffu, s,  o);
        s2 += __shfl_xor_sync(0xffffffffu, s2, o);
    }
    __shared__ float sa[8], sb[8];
    int w = threadIdx.x >> 5, l = threadIdx.x & 31;
    if (l == 0) { sa[w] = s; sb[w] = s2; }
    __syncthreads();
    s = 0.f; s2 = 0.f;
    #pragma unroll
    for (int i = 0; i < 8; i++) { s += sa[i]; s2 += sb[i]; }

    const float mean = s * (1.0f / D_);
    const float var  = s2 * (1.0f / D_) - mean*mean;
    const float rstd = rsqrtf(var + 1e-5f);
    float* o = out + (long)row * D_;
    #pragma unroll
    for (int i = 0; i < 3; i++) {
        int c = threadIdx.x + i*256;
        o[c] = (v[i] - mean) * rstd * gamma[c] + beta[c];
    }
}

// ---------------- Softmax over rows of length 2048, in-place ---------------
__global__ void softmax_kernel(float* __restrict__ s)
{
    float4* p = reinterpret_cast<float4*>(s + (size_t)blockIdx.x * N_);
    const int t = threadIdx.x;
    float4 a = p[t], b = p[t + 256];

    float m = fmaxf(fmaxf(fmaxf(a.x, a.y), fmaxf(a.z, a.w)),
                    fmaxf(fmaxf(b.x, b.y), fmaxf(b.z, b.w)));
    #pragma unroll
    for (int o = 16; o > 0; o >>= 1) m = fmaxf(m, __shfl_xor_sync(0xffffffffu, m, o));
    __shared__ float sm[8];
    int w = t >> 5, l = t & 31;
    if (l == 0) sm[w] = m;
    __syncthreads();
    m = sm[0];
    #pragma unroll
    for (int i = 1; i < 8; i++) m = fmaxf(m, sm[i]);

    a.x = __expf(a.x - m); a.y = __expf(a.y - m); a.z = __expf(a.z - m); a.w = __expf(a.w - m);
    b.x = __expf(b.x - m); b.y = __expf(b.y - m); b.z = __expf(b.z - m); b.w = __expf(b.w - m);
    float sum = a.x + a.y + a.z + a.w + b.x + b.y + b.z + b.w;
    #pragma unroll
    for (int o = 16; o > 0; o >>= 1) sum += __shfl_xor_sync(0xffffffffu, sum, o);
    __shared__ float ss[8];
    if (l == 0) ss[w] = sum;
    __syncthreads();
    sum = 0.f;
    #pragma unroll
    for (int i = 0; i < 8; i++) sum += ss[i];

    const float inv = 1.0f / sum;
    a.x *= inv; a.y *= inv; a.z *= inv; a.w *= inv;
    b.x *= inv; b.y *= inv; b.z *= inv; b.w *= inv;
    p[t] = a; p[t + 256] = b;
}

// ---------------- TF32 tensor-core GEMM with fused epilogue ----------------
// C[z] = act( alpha * A[z] @ op(B[z]) + bias ) + residual
__device__ __forceinline__ unsigned f2tf(float f){
    unsigned u; asm("cvt.rna.tf32.f32 %0, %1;" : "=r"(u) : "f"(f)); return u;
}

template<int BM,int BN,int BK,int WM,int WN,bool TRANSB,bool GELU>
__global__ void __launch_bounds__((BM/WM)*(BN/WN)*32)
mma_gemm(
    const float* __restrict__ A, const float* __restrict__ Bm,
    const float* __restrict__ bias, const float* __restrict__ residual,
    float* __restrict__ C,
    int Mdim, int Ndim, int K, int lda, int ldb, int ldc,
    float alpha, int zdiv,
    long Aout, long Ain, long Bout, long Bin, long Cout, long Cin,
    long biasOut, long biasIn, int ldbias)
{
    constexpr int NWN = BN/WN;
    constexpr int MF = WM/16, NF = WN/8;
    constexpr int THREADS = (BM/WM)*(BN/WN)*32;
    constexpr int SA = BK + 4;     // As row stride (floats)
    constexpr int SB = BN + 8;     // Bs row stride (floats)

    __shared__ float As[2][BM*SA];
    __shared__ float Bs[2][BK*SB];

    const int z  = blockIdx.z;
    const int zo = z / zdiv;
    const int zi = z - zo*zdiv;
    A  += zo*Aout + zi*Ain;
    Bm += zo*Bout + zi*Bin;
    C  += zo*Cout + zi*Cin;
    const float* biasP = bias     ? bias     + zo*biasOut + zi*biasIn : nullptr;
    const float* resP  = residual ? residual + zo*Cout    + zi*Cin    : nullptr;

    const int bm = blockIdx.y * BM;
    const int bn = blockIdx.x * BN;
    const int tid  = threadIdx.x;
    const int wid  = tid >> 5, lane = tid & 31;
    const int wm   = wid / NWN, wn = wid % NWN;
    const int g    = lane >> 2, tg = lane & 3;

    float acc[MF][NF][4];
    #pragma unroll
    for (int i = 0; i < MF; i++)
        #pragma unroll
        for (int j = 0; j < NF; j++)
            #pragma unroll
            for (int c = 0; c < 4; c++) acc[i][j][c] = 0.f;

    constexpr int A_LD = (BM*BK/4)/THREADS;   // float4 per thread
    constexpr int B_LD = (BK*BN/4)/THREADS;

    auto issueA = [&](int buf, int k0){
        #pragma unroll
        for (int it = 0; it < A_LD; it++){
            int i = tid + it*THREADS;
            int r = i/(BK/4), c = (i%(BK/4))*4;
            unsigned dst = (unsigned)__cvta_generic_to_shared(&As[buf][r*SA + c]);
            const float* src = &A[(long)(bm+r)*lda + k0 + c];
            asm volatile("cp.async.cg.shared.global [%0], [%1], 16;\n" :: "r"(dst),"l"(src));
        }
    };
    auto issueB = [&](int buf, int k0){
        if (!TRANSB){
            #pragma unroll
            for (int it = 0; it < B_LD; it++){
                int i = tid + it*THREADS;
                int r = i/(BN/4), c = (i%(BN/4))*4;
                unsigned dst = (unsigned)__cvta_generic_to_shared(&Bs[buf][r*SB + c]);
                const float* src = &Bm[(long)(k0+r)*ldb + bn + c];
                asm volatile("cp.async.cg.shared.global [%0], [%1], 16;\n" :: "r"(dst),"l"(src));
            }
        } else {
            #pragma unroll
            for (int it = 0; it < B_LD; it++){
                int i = tid + it*THREADS;
                int n = i/(BK/4), c = (i%(BK/4))*4;
                float4 v = *reinterpret_cast<const float4*>(&Bm[(long)(bn+n)*ldb + k0 + c]);
                Bs[buf][(c+0)*SB + n] = v.x;
                Bs[buf][(c+1)*SB + n] = v.y;
                Bs[buf][(c+2)*SB + n] = v.z;
                Bs[buf][(c+3)*SB + n] = v.w;
            }
        }
    };

    const int nIter = K / BK;
    issueA(0, 0); issueB(0, 0);
    asm volatile("cp.async.commit_group;\n");

    for (int it = 0; it < nIter; it++){
        const int buf = it & 1;
        if (it + 1 < nIter){
            issueA(buf^1, (it+1)*BK); issueB(buf^1, (it+1)*BK);
            asm volatile("cp.async.commit_group;\n");
            asm volatile("cp.async.wait_group 1;\n");
        } else {
            asm volatile("cp.async.wait_group 0;\n");
        }
        __syncthreads();

        #pragma unroll
        for (int ks = 0; ks < BK/8; ks++){
            unsigned a[MF][4], b[NF][2];
            #pragma unroll
            for (int mf = 0; mf < MF; mf++){
                const int mrow = wm*WM + mf*16;
                a[mf][0] = f2tf(As[buf][(mrow+g  )*SA + ks*8 + tg  ]);
                a[mf][1] = f2tf(As[buf][(mrow+g+8)*SA + ks*8 + tg  ]);
                a[mf][2] = f2tf(As[buf][(mrow+g  )*SA + ks*8 + tg+4]);
                a[mf][3] = f2tf(As[buf][(mrow+g+8)*SA + ks*8 + tg+4]);
            }
            #pragma unroll
            for (int nf = 0; nf < NF; nf++){
                const int ncol = wn*WN + nf*8 + g;
                b[nf][0] = f2tf(Bs[buf][(ks*8+tg  )*SB + ncol]);
                b[nf][1] = f2tf(Bs[buf][(ks*8+tg+4)*SB + ncol]);
            }
            #pragma unroll
            for (int mf = 0; mf < MF; mf++)
                #pragma unroll
                for (int nf = 0; nf < NF; nf++){
                    asm volatile(
                        "mma.sync.aligned.m16n8k8.row.col.f32.tf32.tf32.f32 "
                        "{%0,%1,%2,%3}, {%4,%5,%6,%7}, {%8,%9}, {%0,%1,%2,%3};\n"
                        : "+f"(acc[mf][nf][0]), "+f"(acc[mf][nf][1]),
                          "+f"(acc[mf][nf][2]), "+f"(acc[mf][nf][3])
                        : "r"(a[mf][0]), "r"(a[mf][1]), "r"(a[mf][2]), "r"(a[mf][3]),
                          "r"(b[nf][0]), "r"(b[nf][1]));
                }
        }
        __syncthreads();
    }

    // ---------------- epilogue ----------------
    #pragma unroll
    for (int mf = 0; mf < MF; mf++){
        #pragma unroll
        for (int nf = 0; nf < NF; nf++){
            const int col = bn + wn*WN + nf*8 + tg*2;
            #pragma unroll
            for (int h = 0; h < 2; h++){
                const int row = bm + wm*WM + mf*16 + g + h*8;
                float v0 = acc[mf][nf][h*2+0] * alpha;
                float v1 = acc[mf][nf][h*2+1] * alpha;
                if (biasP){
                    if (ldbias > 0){
                        v0 += biasP[(long)row*ldbias + col];
                        v1 += biasP[(long)row*ldbias + col + 1];
                    } else {
                        v0 += biasP[col];
                        v1 += biasP[col + 1];
                    }
                }
                if (GELU){
                    v0 = 0.5f*v0*(1.0f + erff(v0*0.70710678118654752f));
                    v1 = 0.5f*v1*(1.0f + erff(v1*0.70710678118654752f));
                }
                if (resP){
                    v0 += resP[(long)row*ldc + col];
                    v1 += resP[(long)row*ldc + col + 1];
                }
                *reinterpret_cast<float2*>(&C[(long)row*ldc + col]) = make_float2(v0, v1);
            }
        }
    }
}

// ---------------------------------------------------------------------------
extern "C" void kernel_launch(void* const* d_in, const int* in_sizes, int n_in,
                              void* d_out, int out_size)
{
    const float* x      = (const float*)d_in[0];
    const float* Wqkv   = (const float*)d_in[1];
    const float* Wout   = (const float*)d_in[2];
    const float* gamma1 = (const float*)d_in[3];
    const float* beta1  = (const float*)d_in[4];
    const float* gamma2 = (const float*)d_in[5];
    const float* beta2  = (const float*)d_in[6];
    const float* W1     = (const float*)d_in[7];
    const float* b1     = (const float*)d_in[8];
    const float* W2     = (const float*)d_in[9];
    const float* b2     = (const float*)d_in[10];
    const float* abias  = (const float*)d_in[11];
    float* out = (float*)d_out;

    float *h, *qkv, *sc, *ao, *x1, *ffn;
    cudaGetSymbolAddress((void**)&h,   g_h);
    cudaGetSymbolAddress((void**)&qkv, g_qkv);
    cudaGetSymbolAddress((void**)&sc,  g_scores);
    cudaGetSymbolAddress((void**)&ao,  g_attnout);
    cudaGetSymbolAddress((void**)&x1,  g_x1);
    cudaGetSymbolAddress((void**)&ffn, g_ffn);

    // 1. h = LN(x; gamma1, beta1)
    ln_kernel<<<R_, 256>>>(x, gamma1, beta1, h);

    // 2. qkv = h @ Wqkv   [4096 x 2304]
    mma_gemm<128,128,16,64,32,false,false><<<dim3(QKVC/128, R_/128, 1), 256>>>(
        h, Wqkv, nullptr, nullptr, qkv,
        R_, QKVC, D_, D_, QKVC, QKVC,
        1.0f, 1, 0,0, 0,0, 0,0, 0,0, 0);

    // 3. scores[b,h] = (q @ k^T) * scale + attn_bias[h]
    //    (softmax(d)*softmax(bias) renormalized == softmax(d + bias))
    mma_gemm<128,128,16,64,32,true,false><<<dim3(N_/128, N_/128, B_*H_), 256>>>(
        qkv /*q*/, qkv + H_*DH_ /*k*/, abias, nullptr, sc,
        N_, N_, DH_, QKVC, QKVC, N_,
        0.125f, H_,
        (long)N_*QKVC, (long)DH_,
        (long)N_*QKVC, (long)DH_,
        (long)H_*N_*N_, (long)N_*N_,
        0L, (long)N_*N_, N_);

    // 4. softmax rows
    softmax_kernel<<<B_*H_*N_, 256>>>(sc);

    // 5. attnout[b,h] = attn @ v  (N=64 per head)
    mma_gemm<128,64,16,32,32,false,false><<<dim3(1, N_/128, B_*H_), 256>>>(
        sc, qkv + 2*H_*DH_ /*v*/, nullptr, nullptr, ao,
        N_, DH_, N_, N_, QKVC, D_,
        1.0f, H_,
        (long)H_*N_*N_, (long)N_*N_,
        (long)N_*QKVC, (long)DH_,
        (long)N_*D_, (long)DH_,
        0L, 0L, 0);

    // 6. x1 = attnout @ Wout + x
    mma_gemm<128,128,16,64,32,false,false><<<dim3(D_/128, R_/128, 1), 256>>>(
        ao, Wout, nullptr, x, x1,
        R_, D_, D_, D_, D_, D_,
        1.0f, 1, 0,0, 0,0, 0,0, 0,0, 0);

    // 7. h = LN(x1; gamma2, beta2)
    ln_kernel<<<R_, 256>>>(x1, gamma2, beta2, h);

    // 8. ffn = gelu(h @ W1 + b1)
    mma_gemm<128,128,16,64,32,false,true><<<dim3(M_/128, R_/128, 1), 256>>>(
        h, W1, b1, nullptr, ffn,
        R_, M_, D_, D_, M_, M_,
        1.0f, 1, 0,0, 0,0, 0,0, 0,0, 0);

    // 9. out = ffn @ W2 + b2 + x1
    mma_gemm<128,128,16,64,32,false,false><<<dim3(D_/128, R_/128, 1), 256>>>(
        ffn, W2, b2, x1, out,
        R_, D_, M_, M_, D_, D_,
        1.0f, 1, 0,0, 0,0, 0,0, 0,0, 0);
}

// round 3
// speedup vs baseline: 3.3808x; 1.4183x over previous
#include <cuda_runtime.h>
#include <math.h>

// Problem dims (fixed instance)
#define B_   2
#define N_   2048
#define D_   768
#define H_   12
#define DH_  64
#define M_   3072
#define R_   (B_*N_)          // 4096 token rows
#define QKVC (3*H_*DH_)       // 2304

// ---------------- scratch (device globals; no allocations allowed) ---------
__device__ float g_h[(size_t)R_*D_];
__device__ float g_qkv[(size_t)R_*QKVC];
__device__ float g_attnout[(size_t)R_*D_];
__device__ float g_x1[(size_t)R_*D_];
__device__ float g_ffn[(size_t)R_*M_];

// ---------------- helpers ---------------------------------------------------
__device__ __forceinline__ unsigned f2tf(float f){
    unsigned u; asm("cvt.rna.tf32.f32 %0, %1;" : "=r"(u) : "f"(f)); return u;
}
__device__ __forceinline__ void cpa16(void* dst, const void* src){
    unsigned d = (unsigned)__cvta_generic_to_shared(dst);
    asm volatile("cp.async.cg.shared.global [%0], [%1], 16;\n" :: "r"(d), "l"(src));
}
__device__ __forceinline__ void mma_tf32(float* c, const unsigned* a, unsigned b0, unsigned b1){
    asm volatile("mma.sync.aligned.m16n8k8.row.col.f32.tf32.tf32.f32 "
        "{%0,%1,%2,%3}, {%4,%5,%6,%7}, {%8,%9}, {%0,%1,%2,%3};\n"
        : "+f"(c[0]),"+f"(c[1]),"+f"(c[2]),"+f"(c[3])
        : "r"(a[0]),"r"(a[1]),"r"(a[2]),"r"(a[3]), "r"(b0),"r"(b1));
}

// ---------------- LayerNorm: one block (256 thr) per row of 768 ------------
__global__ void ln_kernel(const float* __restrict__ x,
                          const float* __restrict__ gamma,
                          const float* __restrict__ beta,
                          float* __restrict__ out)
{
    const int row = blockIdx.x;
    const float* xr = x + (long)row * D_;
    float v[3];
    float s = 0.f, s2 = 0.f;
    #pragma unroll
    for (int i = 0; i < 3; i++) {
        v[i] = xr[threadIdx.x + i*256];
        s  += v[i];
        s2 += v[i]*v[i];
    }
    #pragma unroll
    for (int o = 16; o > 0; o >>= 1) {
        s  += __shfl_xor_sync(0xffffffffu, s,  o);
        s2 += __shfl_xor_sync(0xffffffffu, s2, o);
    }
    __shared__ float sa[8], sb[8];
    int w = threadIdx.x >> 5, l = threadIdx.x & 31;
    if (l == 0) { sa[w] = s; sb[w] = s2; }
    __syncthreads();
    s = 0.f; s2 = 0.f;
    #pragma unroll
    for (int i = 0; i < 8; i++) { s += sa[i]; s2 += sb[i]; }

    const float mean = s * (1.0f / D_);
    const float var  = s2 * (1.0f / D_) - mean*mean;
    const float rstd = rsqrtf(var + 1e-5f);
    float* o = out + (long)row * D_;
    #pragma unroll
    for (int i = 0; i < 3; i++) {
        int c = threadIdx.x + i*256;
        o[c] = (v[i] - mean) * rstd * gamma[c] + beta[c];
    }
}

// ---------------- Flash attention -------------------------------------------
// softmax(QK^T*scale + bias) @ V, fused.  128 q-rows per block, 8 warps.
// (softmax(d)*softmax(bias) renormalized == softmax(d + bias))
#define KST 68
#define VST 72
#define PST 132
#define KS_OFF 0
#define VS_OFF (2*128*KST)
#define PS_OFF (2*128*KST + 2*128*VST)
#define FA_SMEM ((2*128*KST + 2*128*VST + 128*PST)*4)

__global__ void __launch_bounds__(256,1)
flash_kernel(const float* __restrict__ qkv,
             const float* __restrict__ bias,
             float* __restrict__ ao)
{
    extern __shared__ float sm[];
    float* Ks = sm + KS_OFF;
    float* Vs = sm + VS_OFF;
    float* Ps = sm + PS_OFF;

    const int qt = blockIdx.x;       // 0..15
    const int hh = blockIdx.y;       // 0..11
    const int bb = blockIdx.z;       // 0..1
    const int q0 = qt*128;
    const long base = (long)bb*N_*QKVC;
    const float* Qg = qkv + base + hh*DH_;
    const float* Kg = qkv + base + H_*DH_ + hh*DH_;
    const float* Vg = qkv + base + 2*H_*DH_ + hh*DH_;
    const float* Bg = bias + (long)hh*N_*N_;

    const int tid = threadIdx.x, wid = tid>>5, lane = tid&31;
    const int g = lane>>2, tg = lane&3;
    const int mrow = wid*16;

    // prologue loads: group0 = {Q, K0, V0}, group1 = {K1, V1}
    {
        #pragma unroll
        for (int it = 0; it < 8; it++){
            int i = tid + it*256;
            int r = i >> 4, c4 = (i & 15)*4;
            cpa16(&Ps[r*KST + c4], &Qg[(long)(q0+r)*QKVC + c4]);
            cpa16(&Ks[r*KST + c4], &Kg[(long)r*QKVC + c4]);
            cpa16(&Vs[r*VST + c4], &Vg[(long)r*QKVC + c4]);
        }
        asm volatile("cp.async.commit_group;\n");
        #pragma unroll
        for (int it = 0; it < 8; it++){
            int i = tid + it*256;
            int r = i >> 4, c4 = (i & 15)*4;
            cpa16(&Ks[128*KST + r*KST + c4], &Kg[(long)(128+r)*QKVC + c4]);
            cpa16(&Vs[128*VST + r*VST + c4], &Vg[(long)(128+r)*QKVC + c4]);
        }
        asm volatile("cp.async.commit_group;\n");
    }

    asm volatile("cp.async.wait_group 1;\n");
    __syncthreads();

    // Q fragments (loop-invariant)
    unsigned qf[8][4];
    #pragma unroll
    for (int ks = 0; ks < 8; ks++){
        qf[ks][0] = f2tf(Ps[(mrow+g  )*KST + ks*8 + tg  ]);
        qf[ks][1] = f2tf(Ps[(mrow+g+8)*KST + ks*8 + tg  ]);
        qf[ks][2] = f2tf(Ps[(mrow+g  )*KST + ks*8 + tg+4]);
        qf[ks][3] = f2tf(Ps[(mrow+g+8)*KST + ks*8 + tg+4]);
    }
    __syncwarp();

    float m0 = -1e30f, m1 = -1e30f, l0 = 0.f, l1 = 0.f;
    float o[8][4];
    #pragma unroll
    for (int i = 0; i < 8; i++)
        #pragma unroll
        for (int c = 0; c < 4; c++) o[i][c] = 0.f;

    for (int j = 0; j < 16; j++){
        if (j < 15) asm volatile("cp.async.wait_group 1;\n");
        else        asm volatile("cp.async.wait_group 0;\n");
        __syncthreads();
        const float* Kb = &Ks[(j&1)*128*KST];
        const float* Vb = &Vs[(j&1)*128*VST];

        // ---- S = Q @ K^T ----
        float s[16][4];
        #pragma unroll
        for (int nf = 0; nf < 16; nf++)
            #pragma unroll
            for (int c = 0; c < 4; c++) s[nf][c] = 0.f;
        #pragma unroll
        for (int nf = 0; nf < 16; nf++){
            #pragma unroll
            for (int ks = 0; ks < 8; ks++){
                unsigned b0 = f2tf(Kb[(nf*8+g)*KST + ks*8 + tg  ]);
                unsigned b1 = f2tf(Kb[(nf*8+g)*KST + ks*8 + tg+4]);
                mma_tf32(s[nf], qf[ks], b0, b1);
            }
        }

        // ---- scale + bias ----
        const float* br0 = Bg + (long)(q0+mrow+g  )*N_ + j*128 + 2*tg;
        const float* br1 = Bg + (long)(q0+mrow+g+8)*N_ + j*128 + 2*tg;
        #pragma unroll
        for (int nf = 0; nf < 16; nf++){
            float2 t0 = *reinterpret_cast<const float2*>(br0 + nf*8);
            float2 t1 = *reinterpret_cast<const float2*>(br1 + nf*8);
            s[nf][0] = fmaf(s[nf][0], 0.125f, t0.x);
            s[nf][1] = fmaf(s[nf][1], 0.125f, t0.y);
            s[nf][2] = fmaf(s[nf][2], 0.125f, t1.x);
            s[nf][3] = fmaf(s[nf][3], 0.125f, t1.y);
        }

        // ---- online softmax ----
        float mt0 = -1e30f, mt1 = -1e30f;
        #pragma unroll
        for (int nf = 0; nf < 16; nf++){
            mt0 = fmaxf(mt0, fmaxf(s[nf][0], s[nf][1]));
            mt1 = fmaxf(mt1, fmaxf(s[nf][2], s[nf][3]));
        }
        mt0 = fmaxf(mt0, __shfl_xor_sync(0xffffffffu, mt0, 1));
        mt0 = fmaxf(mt0, __shfl_xor_sync(0xffffffffu, mt0, 2));
        mt1 = fmaxf(mt1, __shfl_xor_sync(0xffffffffu, mt1, 1));
        mt1 = fmaxf(mt1, __shfl_xor_sync(0xffffffffu, mt1, 2));
        const float mn0 = fmaxf(m0, mt0), mn1 = fmaxf(m1, mt1);
        const float cr0 = __expf(m0 - mn0), cr1 = __expf(m1 - mn1);
        m0 = mn0; m1 = mn1;

        float ls0 = 0.f, ls1 = 0.f;
        float* pr0 = &Ps[(mrow+g  )*PST + 2*tg];
        float* pr1 = &Ps[(mrow+g+8)*PST + 2*tg];
        #pragma unroll
        for (int nf = 0; nf < 16; nf++){
            float p0 = __expf(s[nf][0] - m0);
            float p1 = __expf(s[nf][1] - m0);
            float p2 = __expf(s[nf][2] - m1);
            float p3 = __expf(s[nf][3] - m1);
            ls0 += p0 + p1; ls1 += p2 + p3;
            *reinterpret_cast<float2*>(pr0 + nf*8) =
                make_float2(__uint_as_float(f2tf(p0)), __uint_as_float(f2tf(p1)));
            *reinterpret_cast<float2*>(pr1 + nf*8) =
                make_float2(__uint_as_float(f2tf(p2)), __uint_as_float(f2tf(p3)));
        }
        ls0 += __shfl_xor_sync(0xffffffffu, ls0, 1);
        ls0 += __shfl_xor_sync(0xffffffffu, ls0, 2);
        ls1 += __shfl_xor_sync(0xffffffffu, ls1, 1);
        ls1 += __shfl_xor_sync(0xffffffffu, ls1, 2);
        l0 = l0*cr0 + ls0;
        l1 = l1*cr1 + ls1;
        #pragma unroll
        for (int nf = 0; nf < 8; nf++){
            o[nf][0] *= cr0; o[nf][1] *= cr0;
            o[nf][2] *= cr1; o[nf][3] *= cr1;
        }
        __syncwarp();

        // ---- O += P @ V ----
        #pragma unroll
        for (int ks2 = 0; ks2 < 16; ks2++){
            unsigned a[4];
            a[0] = __float_as_uint(Ps[(mrow+g  )*PST + ks2*8 + tg  ]);
            a[1] = __float_as_uint(Ps[(mrow+g+8)*PST + ks2*8 + tg  ]);
            a[2] = __float_as_uint(Ps[(mrow+g  )*PST + ks2*8 + tg+4]);
            a[3] = __float_as_uint(Ps[(mrow+g+8)*PST + ks2*8 + tg+4]);
            #pragma unroll
            for (int nf = 0; nf < 8; nf++){
                unsigned b0 = f2tf(Vb[(ks2*8+tg  )*VST + nf*8 + g]);
                unsigned b1 = f2tf(Vb[(ks2*8+tg+4)*VST + nf*8 + g]);
                mma_tf32(o[nf], a, b0, b1);
            }
        }

        __syncthreads();
        if (j + 2 < 16){
            const int buf = j & 1;     // (j+2) & 1
            const float* kp = Kg + (long)(j+2)*128*QKVC;
            const float* vp = Vg + (long)(j+2)*128*QKVC;
            #pragma unroll
            for (int it = 0; it < 8; it++){
                int i = tid + it*256;
                int r = i >> 4, c4 = (i & 15)*4;
                cpa16(&Ks[buf*128*KST + r*KST + c4], kp + (long)r*QKVC + c4);
                cpa16(&Vs[buf*128*VST + r*VST + c4], vp + (long)r*QKVC + c4);
            }
            asm volatile("cp.async.commit_group;\n");
        }
    }

    // ---- epilogue: O / l ----
    const float inv0 = 1.0f / l0, inv1 = 1.0f / l1;
    float* o0 = ao + (long)(bb*N_ + q0 + mrow + g  )*D_ + hh*DH_ + 2*tg;
    float* o1 = ao + (long)(bb*N_ + q0 + mrow + g+8)*D_ + hh*DH_ + 2*tg;
    #pragma unroll
    for (int nf = 0; nf < 8; nf++){
        *reinterpret_cast<float2*>(o0 + nf*8) = make_float2(o[nf][0]*inv0, o[nf][1]*inv0);
        *reinterpret_cast<float2*>(o1 + nf*8) = make_float2(o[nf][2]*inv1, o[nf][3]*inv1);
    }
}

// ---------------- TF32 tensor-core GEMM with fused epilogue ----------------
// C = act( A @ B + bias ) + residual        (row-major A,B,C)
template<int BM,int BN,int BK,int WM,int WN,bool GELU>
__global__ void __launch_bounds__((BM/WM)*(BN/WN)*32)
mma_gemm(
    const float* __restrict__ A, const float* __restrict__ Bm,
    const float* __restrict__ bias, const float* __restrict__ residual,
    float* __restrict__ C,
    int K, int lda, int ldb, int ldc)
{
    constexpr int NWN = BN/WN;
    constexpr int MF = WM/16, NF = WN/8;
    constexpr int THREADS = (BM/WM)*(BN/WN)*32;
    constexpr int SA = BK + 4;
    constexpr int SB = BN + 8;

    extern __shared__ float smg[];
    float* As = smg;                    // [2][BM*SA]
    float* Bs = smg + 2*BM*SA;          // [2][BK*SB]

    const int bm = blockIdx.y * BM;
    const int bn = blockIdx.x * BN;
    const int tid  = threadIdx.x;
    const int wid  = tid >> 5, lane = tid & 31;
    const int wm   = wid / NWN, wn = wid % NWN;
    const int g    = lane >> 2, tg = lane & 3;

    float acc[MF][NF][4];
    #pragma unroll
    for (int i = 0; i < MF; i++)
        #pragma unroll
        for (int j = 0; j < NF; j++)
            #pragma unroll
            for (int c = 0; c < 4; c++) acc[i][j][c] = 0.f;

    constexpr int A_LD = (BM*BK/4)/THREADS;
    constexpr int B_LD = (BK*BN/4)/THREADS;

    auto issue = [&](int buf, int k0){
        #pragma unroll
        for (int it = 0; it < A_LD; it++){
            int i = tid + it*THREADS;
            int r = i/(BK/4), c = (i%(BK/4))*4;
            cpa16(&As[buf*BM*SA + r*SA + c], &A[(long)(bm+r)*lda + k0 + c]);
        }
        #pragma unroll
        for (int it = 0; it < B_LD; it++){
            int i = tid + it*THREADS;
            int r = i/(BN/4), c = (i%(BN/4))*4;
            cpa16(&Bs[buf*BK*SB + r*SB + c], &Bm[(long)(k0+r)*ldb + bn + c]);
        }
        asm volatile("cp.async.commit_group;\n");
    };

    const int nIter = K / BK;
    issue(0, 0);

    for (int it = 0; it < nIter; it++){
        const int buf = it & 1;
        if (it + 1 < nIter){
            issue(buf^1, (it+1)*BK);
            asm volatile("cp.async.wait_group 1;\n");
        } else {
            asm volatile("cp.async.wait_group 0;\n");
        }
        __syncthreads();
        const float* Ab = &As[buf*BM*SA];
        const float* Bb = &Bs[buf*BK*SB];

        #pragma unroll
        for (int ks = 0; ks < BK/8; ks++){
            unsigned a[MF][4], b[NF][2];
            #pragma unroll
            for (int mf = 0; mf < MF; mf++){
                const int mrow = wm*WM + mf*16;
                a[mf][0] = f2tf(Ab[(mrow+g  )*SA + ks*8 + tg  ]);
                a[mf][1] = f2tf(Ab[(mrow+g+8)*SA + ks*8 + tg  ]);
                a[mf][2] = f2tf(Ab[(mrow+g  )*SA + ks*8 + tg+4]);
                a[mf][3] = f2tf(Ab[(mrow+g+8)*SA + ks*8 + tg+4]);
            }
            #pragma unroll
            for (int nf = 0; nf < NF; nf++){
                const int ncol = wn*WN + nf*8 + g;
                b[nf][0] = f2tf(Bb[(ks*8+tg  )*SB + ncol]);
                b[nf][1] = f2tf(Bb[(ks*8+tg+4)*SB + ncol]);
            }
            #pragma unroll
            for (int mf = 0; mf < MF; mf++)
                #pragma unroll
                for (int nf = 0; nf < NF; nf++)
                    mma_tf32(acc[mf][nf], a[mf], b[nf][0], b[nf][1]);
        }
        __syncthreads();
    }

    #pragma unroll
    for (int mf = 0; mf < MF; mf++){
        #pragma unroll
        for (int nf = 0; nf < NF; nf++){
            const int col = bn + wn*WN + nf*8 + tg*2;
            #pragma unroll
            for (int h = 0; h < 2; h++){
                const int row = bm + wm*WM + mf*16 + g + h*8;
                float v0 = acc[mf][nf][h*2+0];
                float v1 = acc[mf][nf][h*2+1];
                if (bias){
                    v0 += bias[col];
                    v1 += bias[col + 1];
                }
                if (GELU){
                    v0 = 0.5f*v0*(1.0f + erff(v0*0.70710678118654752f));
                    v1 = 0.5f*v1*(1.0f + erff(v1*0.70710678118654752f));
                }
                if (residual){
                    v0 += residual[(long)row*ldc + col];
                    v1 += residual[(long)row*ldc + col + 1];
                }
                *reinterpret_cast<float2*>(&C[(long)row*ldc + col]) = make_float2(v0, v1);
            }
        }
    }
}

// ---------------------------------------------------------------------------
#define GEMM_SMEM ((2*128*36 + 2*32*136)*4)

extern "C" void kernel_launch(void* const* d_in, const int* in_sizes, int n_in,
                              void* d_out, int out_size)
{
    const float* x      = (const float*)d_in[0];
    const float* Wqkv   = (const float*)d_in[1];
    const float* Wout   = (const float*)d_in[2];
    const float* gamma1 = (const float*)d_in[3];
    const float* beta1  = (const float*)d_in[4];
    const float* gamma2 = (const float*)d_in[5];
    const float* beta2  = (const float*)d_in[6];
    const float* W1     = (const float*)d_in[7];
    const float* b1     = (const float*)d_in[8];
    const float* W2     = (const float*)d_in[9];
    const float* b2     = (const float*)d_in[10];
    const float* abias  = (const float*)d_in[11];
    float* out = (float*)d_out;

    float *h, *qkv, *ao, *x1, *ffn;
    cudaGetSymbolAddress((void**)&h,   g_h);
    cudaGetSymbolAddress((void**)&qkv, g_qkv);
    cudaGetSymbolAddress((void**)&ao,  g_attnout);
    cudaGetSymbolAddress((void**)&x1,  g_x1);
    cudaGetSymbolAddress((void**)&ffn, g_ffn);

    cudaFuncSetAttribute(flash_kernel, cudaFuncAttributeMaxDynamicSharedMemorySize, FA_SMEM);
    cudaFuncSetAttribute(mma_gemm<128,128,32,64,32,false>, cudaFuncAttributeMaxDynamicSharedMemorySize, GEMM_SMEM);
    cudaFuncSetAttribute(mma_gemm<128,128,32,64,32,true>,  cudaFuncAttributeMaxDynamicSharedMemorySize, GEMM_SMEM);

    // 1. h = LN(x)
    ln_kernel<<<R_, 256>>>(x, gamma1, beta1, h);

    // 2. qkv = h @ Wqkv
    mma_gemm<128,128,32,64,32,false><<<dim3(QKVC/128, R_/128), 256, GEMM_SMEM>>>(
        h, Wqkv, nullptr, nullptr, qkv, D_, D_, QKVC, QKVC);

    // 3-5. fused flash attention -> ao
    flash_kernel<<<dim3(N_/128, H_, B_), 256, FA_SMEM>>>(qkv, abias, ao);

    // 6. x1 = ao @ Wout + x
    mma_gemm<128,128,32,64,32,false><<<dim3(D_/128, R_/128), 256, GEMM_SMEM>>>(
        ao, Wout, nullptr, x, x1, D_, D_, D_, D_);

    // 7. h = LN(x1)
    ln_kernel<<<R_, 256>>>(x1, gamma2, beta2, h);

    // 8. ffn = gelu(h @ W1 + b1)
    mma_gemm<128,128,32,64,32,true><<<dim3(M_/128, R_/128), 256, GEMM_SMEM>>>(
        h, W1, b1, nullptr, ffn, D_, D_, M_, M_);

    // 9. out = ffn @ W2 + b2 + x1
    mma_gemm<128,128,32,64,32,false><<<dim3(D_/128, R_/128), 256, GEMM_SMEM>>>(
        ffn, W2, b2, x1, out, M_, M_, D_, D_);
}